// round 9
// baseline (speedup 1.0000x reference)
#include <cuda_runtime.h>

#define B_      8
#define T_      2048
#define DMODEL  512
#define NHEADS  8
#define HDIM    64
#define BT_     (B_*T_)

// Scratch (device globals) — EXACTLY the R2 footprint (128 MiB): proven safe.
__device__ float g_q[B_*NHEADS*T_*HDIM];   // [b,h,t,d] tf32 bits after rope
__device__ float g_k[B_*NHEADS*T_*HDIM];   // [b,h,t,d] tf32 bits after rope
__device__ float g_v[B_*NHEADS*T_*HDIM];   // [b,h,d,t] TRANSPOSED tf32 bits
__device__ float g_y[BT_*DMODEL];          // tf32 bits (flash epilogue)

// ---------------------------------------------------------------------------
// helpers
// ---------------------------------------------------------------------------
__device__ __forceinline__ unsigned f2tf(float x) {
    unsigned u;
    asm("cvt.rna.tf32.f32 %0, %1;" : "=r"(u) : "f"(x));
    return u;
}
__device__ __forceinline__ float f2tf_f(float x) { return __uint_as_float(f2tf(x)); }

__device__ __forceinline__ void mma_tf32(float c[4], const unsigned a[4], const unsigned b[2]) {
    asm volatile(
        "mma.sync.aligned.m16n8k8.row.col.f32.tf32.tf32.f32 "
        "{%0,%1,%2,%3},{%4,%5,%6,%7},{%8,%9},{%0,%1,%2,%3};"
        : "+f"(c[0]), "+f"(c[1]), "+f"(c[2]), "+f"(c[3])
        : "r"(a[0]), "r"(a[1]), "r"(a[2]), "r"(a[3]), "r"(b[0]), "r"(b[1]));
}

__device__ __forceinline__ void ldsm4(unsigned& d0, unsigned& d1, unsigned& d2, unsigned& d3,
                                      unsigned saddr) {
    asm volatile("ldmatrix.sync.aligned.m8n8.x4.shared.b16 {%0,%1,%2,%3}, [%4];"
                 : "=r"(d0), "=r"(d1), "=r"(d2), "=r"(d3) : "r"(saddr));
}

__device__ __forceinline__ void cp16(void* smem, const void* g) {
    unsigned s = (unsigned)__cvta_generic_to_shared(smem);
    asm volatile("cp.async.cg.shared.global [%0], [%1], 16;" :: "r"(s), "l"(g));
}
__device__ __forceinline__ void cp_commit() { asm volatile("cp.async.commit_group;"); }

// ---------------------------------------------------------------------------
// tf32 GEMM — 3-stage cp.async ring, k-step 16, 3 CTAs/SM (24 warps).
// 128x128 tiles, 256 threads (8 warps 2x4), warp tile 64x32.
// A-fragments via ldmatrix.x4; CVT_A=false when A (g_y) is pre-rounded.
// SCATTER: epilogue scatters qkv (V transposed+rounded); else writes Out fp32.
// ---------------------------------------------------------------------------
#define AS_STG (128*20)
#define BS_STG (16*136)
#define GEMM_SMEM (3*(AS_STG + BS_STG)*4)   // 56832 B -> 3 CTAs/SM by smem

template<int N, bool SCATTER, bool CVT_A>
__global__ __launch_bounds__(256, 3) void gemm_tf32_kernel(
    const float* __restrict__ A, const float* __restrict__ W,
    const float* __restrict__ bias, float* __restrict__ Out)
{
    const int K = DMODEL;
    extern __shared__ __align__(16) float smg[];
    float* Asg = smg;                 // [3][128][20]
    float* Bsg = smg + 3*AS_STG;      // [3][16][136]

    int tid  = threadIdx.x;
    int lane = tid & 31, warp = tid >> 5;
    int q = lane & 3, r = lane >> 2;
    int wr = warp >> 2, wc = warp & 3;
    int r0 = blockIdx.y << 7, c0 = blockIdx.x << 7;

    const float* Aptr = SCATTER ? A : g_y;

    unsigned AsB = (unsigned)__cvta_generic_to_shared(Asg);
    unsigned la  = ((lane & 15)*20 + (lane >> 4)*4) * 4;   // A-type LDSM lane offset

    auto issue_tile = [&](int tile, int st) {
        int k0 = tile << 4;
        #pragma unroll
        for (int e = 0; e < 2; e++) {
            int idx = e*256 + tid;
            int row = idx >> 2, kq = idx & 3;
            cp16(&Asg[(st*128 + row)*20 + kq*4], &Aptr[(size_t)(r0+row)*K + k0 + kq*4]);
        }
        #pragma unroll
        for (int e = 0; e < 2; e++) {
            int idx = e*256 + tid;
            int kr = idx >> 5, nq = idx & 31;
            cp16(&Bsg[st*BS_STG + kr*136 + nq*4], &W[(size_t)(k0+kr)*N + c0 + nq*4]);
        }
        cp_commit();
    };

    float acc[4][4][4];
    #pragma unroll
    for (int mi = 0; mi < 4; mi++)
        #pragma unroll
        for (int ni = 0; ni < 4; ni++)
            #pragma unroll
            for (int e = 0; e < 4; e++) acc[mi][ni][e] = 0.f;

    // ---- prologue: 2 tiles in flight
    issue_tile(0, 0);
    issue_tile(1, 1);

    int st_use = 0, st_nxt = 2;
    for (int it = 0; it < 32; it++) {
        if (it + 2 < 32) asm volatile("cp.async.wait_group 1;");
        else             asm volatile("cp.async.wait_group 0;");
        __syncthreads();                 // tile 'it' visible; stage st_nxt free
        if (it + 2 < 32) {
            issue_tile(it + 2, st_nxt);
            st_nxt = (st_nxt == 2) ? 0 : st_nxt + 1;
        }

        int st = st_use;
        #pragma unroll
        for (int ks = 0; ks < 2; ks++) {
            unsigned a[4][4], b[4][2];
            #pragma unroll
            for (int mi = 0; mi < 4; mi++) {
                unsigned addr = AsB + ((st*AS_STG + (wr*64 + mi*16)*20 + ks*8) << 2) + la;
                ldsm4(a[mi][0], a[mi][1], a[mi][2], a[mi][3], addr);
                if (CVT_A) {
                    a[mi][0] = f2tf(__uint_as_float(a[mi][0]));
                    a[mi][1] = f2tf(__uint_as_float(a[mi][1]));
                    a[mi][2] = f2tf(__uint_as_float(a[mi][2]));
                    a[mi][3] = f2tf(__uint_as_float(a[mi][3]));
                }
            }
            #pragma unroll
            for (int ni = 0; ni < 4; ni++) {
                int nb2 = wc*32 + ni*8;
                b[ni][0] = f2tf(Bsg[st*BS_STG + (ks*8 + q    )*136 + nb2 + r]);
                b[ni][1] = f2tf(Bsg[st*BS_STG + (ks*8 + q + 4)*136 + nb2 + r]);
            }
            #pragma unroll
            for (int mi = 0; mi < 4; mi++)
                #pragma unroll
                for (int ni = 0; ni < 4; ni++)
                    mma_tf32(acc[mi][ni], a[mi], b[ni]);
        }
        st_use = (st_use == 2) ? 0 : st_use + 1;
    }

    #pragma unroll
    for (int mi = 0; mi < 4; mi++) {
        #pragma unroll
        for (int half = 0; half < 2; half++) {
            int row = r0 + wr*64 + mi*16 + r + half*8;
            #pragma unroll
            for (int ni = 0; ni < 4; ni++) {
                int col = c0 + wc*32 + ni*8 + 2*q;
                float v0 = acc[mi][ni][half*2+0] + bias[col];
                float v1 = acc[mi][ni][half*2+1] + bias[col+1];
                if (SCATTER) {
                    int b_ = row >> 11, t = row & (T_-1);
                    int proj = col >> 9;
                    int dm = col & 511;
                    int h = dm >> 6, d = dm & 63;
                    int bh = (b_<<3) + h;
                    if (proj == 2) {
                        g_v[((size_t)bh*HDIM + d    )*T_ + t] = f2tf_f(v0);
                        g_v[((size_t)bh*HDIM + d + 1)*T_ + t] = f2tf_f(v1);
                    } else {
                        float* dst = (proj == 0) ? g_q : g_k;
                        *(float2*)&dst[((size_t)bh*T_ + t)*HDIM + d] = make_float2(v0, v1);
                    }
                } else {
                    *(float2*)&Out[(size_t)row*N + col] = make_float2(v0, v1);
                }
            }
        }
    }
}

// ---------------------------------------------------------------------------
// RoPE on q (scaled by 1/sqrt(D)) and k, in place; writes tf32 bits
// ---------------------------------------------------------------------------
__global__ void rope_kernel()
{
    int idx = blockIdx.x*blockDim.x + threadIdx.x;   // B*H*T*32
    int i  = idx & 31;
    int t  = (idx >> 5) & (T_-1);
    int bh = idx >> 16;
    float invf = exp2f(-(float)i * 0.4152410118609203f);
    float ang  = (float)t * invf;
    float sn, cs;
    sincosf(ang, &sn, &cs);
    int base = (bh*T_ + t)*HDIM + i;
    float q1 = g_q[base], q2 = g_q[base+32];
    g_q[base]    = f2tf_f((q1*cs - q2*sn) * 0.125f);
    g_q[base+32] = f2tf_f((q2*cs + q1*sn) * 0.125f);
    float k1 = g_k[base], k2 = g_k[base+32];
    g_k[base]    = f2tf_f(k1*cs - k2*sn);
    g_k[base+32] = f2tf_f(k2*cs + k1*sn);
}

// ---------------------------------------------------------------------------
// Causal flash attention — UNCHANGED from R8 (passing, 3 CTAs/SM).
//   Kn [2][64][68]  natural [key][d]   -> S-mma B frags via ldmatrix.x4
//   Vn [64][68]     TRANSPOSED [d][key]-> PV-mma B frags via ldmatrix.x4
//   QP [64][76]     Q staging / per-warp P -> A frags via ldmatrix.x4
// ---------------------------------------------------------------------------
#define KN_S 68
#define VN_S 68
#define QP_S 76
#define FLASH_SMEM ((2*64*KN_S + 64*VN_S + 64*QP_S)*4)   // 71680 B

__global__ __launch_bounds__(128, 3) void flash_tf32_kernel()
{
    extern __shared__ __align__(16) float sm[];
    float* Kn = sm;
    float* Vn = sm + 2*64*KN_S;
    float* QP = sm + 2*64*KN_S + 64*VN_S;

    int tid  = threadIdx.x;
    int lane = tid & 31, w = tid >> 5;
    int q = lane & 3, r = lane >> 2;
    int bh = blockIdx.x;
    int qt = 31 - (int)blockIdx.y;      // heavy tiles first
    int q0 = qt << 6;

    unsigned smB = (unsigned)__cvta_generic_to_shared(sm);
    unsigned KnB = smB;
    unsigned VnB = smB + 2*64*KN_S*4;
    unsigned QPB = smB + (2*64*KN_S + 64*VN_S)*4;
    unsigned lb  = ((lane & 7)*KN_S + (lane >> 3)*4) * 4;   // B-type LDSM (KN_S==VN_S)
    unsigned lpa = ((lane & 15)*QP_S + (lane >> 4)*4) * 4;  // A-type LDSM in QP

    const float* Kbase = g_k + (size_t)bh*T_*HDIM;          // [key][d]
    const float* Vbase = g_v + (size_t)bh*HDIM*T_;          // [d][key]

    // ---- prefetch K0 + V0 (one group)
    #pragma unroll
    for (int e = 0; e < 8; e++) {
        int idx = e*128 + tid;
        int rr = idx >> 4, c4 = (idx & 15) << 2;
        cp16(&Kn[rr*KN_S + c4], &Kbase[rr*HDIM + c4]);
        cp16(&Vn[rr*VN_S + c4], &Vbase[(size_t)rr*T_ + c4]);
    }
    cp_commit();

    // ---- stage Q tile (tf32 bits already)
    const float* Qg = g_q + ((size_t)bh*T_ + q0)*HDIM;
    #pragma unroll
    for (int it = 0; it < 8; it++) {
        int idx = it*128 + tid;
        int rr = idx >> 4, cc = (idx & 15) << 2;
        *(float4*)&QP[rr*QP_S + cc] = *(const float4*)&Qg[rr*HDIM + cc];
    }
    __syncthreads();

    // ---- Q fragments in registers (A-type ldmatrix, 8x)
    unsigned qa[8][4];
    #pragma unroll
    for (int kk = 0; kk < 8; kk++) {
        unsigned addr = QPB + ((w*16*QP_S + kk*8) << 2) + lpa;
        ldsm4(qa[kk][0], qa[kk][1], qa[kk][2], qa[kk][3], addr);
    }

    float o[8][4];
    float m_[2] = {-1e30f, -1e30f};
    float l_[2] = {0.f, 0.f};
    #pragma unroll
    for (int ni = 0; ni < 8; ni++)
        #pragma unroll
        for (int e = 0; e < 4; e++) o[ni][e] = 0.f;

    for (int kt = 0; kt <= qt; kt++) {
        // prefetch K(t+1) (double buffer), then wait for K(t) + V(t).
        if (kt < qt) {
            int k1 = (kt + 1) << 6;
            int nb = (kt + 1) & 1;
            const float* Kg1 = Kbase + (size_t)k1*HDIM;
            #pragma unroll
            for (int e = 0; e < 8; e++) {
                int idx = e*128 + tid;
                int rr = idx >> 4, c4 = (idx & 15) << 2;
                cp16(&Kn[(nb*64 + rr)*KN_S + c4], &Kg1[rr*HDIM + c4]);
            }
            cp_commit();
            asm volatile("cp.async.wait_group 1;");
        } else {
            asm volatile("cp.async.wait_group 0;");
        }
        __syncthreads();

        int buf = kt & 1;
        unsigned KbB = KnB + buf*64*KN_S*4;

        // ---- S = Q @ K^T
        float s[8][4];
        #pragma unroll
        for (int ni = 0; ni < 8; ni++)
            #pragma unroll
            for (int e = 0; e < 4; e++) s[ni][e] = 0.f;

        #pragma unroll
        for (int ni = 0; ni < 8; ni++) {
            #pragma unroll
            for (int kp = 0; kp < 4; kp++) {
                unsigned b0, b1, b2, b3;
                ldsm4(b0, b1, b2, b3, KbB + ((ni*8*KN_S + kp*16) << 2) + lb);
                unsigned bb0[2] = {b0, b1};
                unsigned bb1[2] = {b2, b3};
                mma_tf32(s[ni], qa[2*kp],     bb0);
                mma_tf32(s[ni], qa[2*kp + 1], bb1);
            }
        }

        // ---- causal mask (diagonal tile only)
        if (kt == qt) {
            int rowA = q0 + w*16 + r;
            int rowB = rowA + 8;
            int k0 = kt << 6;
            #pragma unroll
            for (int ni = 0; ni < 8; ni++) {
                int colb = k0 + ni*8 + 2*q;
                if (colb     > rowA) s[ni][0] = -1e30f;
                if (colb + 1 > rowA) s[ni][1] = -1e30f;
                if (colb     > rowB) s[ni][2] = -1e30f;
                if (colb + 1 > rowB) s[ni][3] = -1e30f;
            }
        }

        // ---- online softmax
        float mxA = -1e30f, mxB = -1e30f;
        #pragma unroll
        for (int ni = 0; ni < 8; ni++) {
            mxA = fmaxf(mxA, fmaxf(s[ni][0], s[ni][1]));
            mxB = fmaxf(mxB, fmaxf(s[ni][2], s[ni][3]));
        }
        mxA = fmaxf(mxA, __shfl_xor_sync(0xffffffffu, mxA, 1));
        mxA = fmaxf(mxA, __shfl_xor_sync(0xffffffffu, mxA, 2));
        mxB = fmaxf(mxB, __shfl_xor_sync(0xffffffffu, mxB, 1));
        mxB = fmaxf(mxB, __shfl_xor_sync(0xffffffffu, mxB, 2));
        float mnA = fmaxf(m_[0], mxA), mnB = fmaxf(m_[1], mxB);
        float alA = __expf(m_[0] - mnA), alB = __expf(m_[1] - mnB);
        m_[0] = mnA; m_[1] = mnB;
        float sA = 0.f, sB = 0.f;
        #pragma unroll
        for (int ni = 0; ni < 8; ni++) {
            s[ni][0] = __expf(s[ni][0] - mnA);
            s[ni][1] = __expf(s[ni][1] - mnA);
            s[ni][2] = __expf(s[ni][2] - mnB);
            s[ni][3] = __expf(s[ni][3] - mnB);
            sA += s[ni][0] + s[ni][1];
            sB += s[ni][2] + s[ni][3];
        }
        sA += __shfl_xor_sync(0xffffffffu, sA, 1);
        sA += __shfl_xor_sync(0xffffffffu, sA, 2);
        sB += __shfl_xor_sync(0xffffffffu, sB, 1);
        sB += __shfl_xor_sync(0xffffffffu, sB, 2);
        l_[0] = l_[0]*alA + sA;
        l_[1] = l_[1]*alB + sB;
        #pragma unroll
        for (int ni = 0; ni < 8; ni++) {
            o[ni][0] *= alA; o[ni][1] *= alA;
            o[ni][2] *= alB; o[ni][3] *= alB;
        }

        // ---- stage P (tf32 bits) into per-warp rows of QP
        __syncwarp();
        {
            int rb = w*16 + r;
            #pragma unroll
            for (int ni = 0; ni < 8; ni++) {
                *(float2*)&QP[(rb    )*QP_S + ni*8 + 2*q] =
                    make_float2(f2tf_f(s[ni][0]), f2tf_f(s[ni][1]));
                *(float2*)&QP[(rb + 8)*QP_S + ni*8 + 2*q] =
                    make_float2(f2tf_f(s[ni][2]), f2tf_f(s[ni][3]));
            }
        }
        __syncwarp();

        // ---- O += P @ V  (P: A-type ldmatrix; V: B-type ldmatrix)
        #pragma unroll
        for (int kp = 0; kp < 4; kp++) {
            unsigned paA[4], paB[4];
            ldsm4(paA[0], paA[1], paA[2], paA[3],
                  QPB + ((w*16*QP_S + (2*kp    )*8) << 2) + lpa);
            ldsm4(paB[0], paB[1], paB[2], paB[3],
                  QPB + ((w*16*QP_S + (2*kp + 1)*8) << 2) + lpa);
            #pragma unroll
            for (int ni = 0; ni < 8; ni++) {
                unsigned v0, v1, v2, v3;
                ldsm4(v0, v1, v2, v3, VnB + ((ni*8*VN_S + kp*16) << 2) + lb);
                unsigned vb0[2] = {v0, v1};
                unsigned vb1[2] = {v2, v3};
                mma_tf32(o[ni], paA, vb0);
                mma_tf32(o[ni], paB, vb1);
            }
        }

        // ---- V(t+1) into the single V buffer, after ALL warps finished PV(t)
        if (kt < qt) {
            __syncthreads();
            int k1 = (kt + 1) << 6;
            #pragma unroll
            for (int e = 0; e < 8; e++) {
                int idx = e*128 + tid;
                int rr = idx >> 4, c4 = (idx & 15) << 2;
                cp16(&Vn[rr*VN_S + c4], &Vbase[(size_t)rr*T_ + k1 + c4]);
            }
            cp_commit();
        }
    }

    // ---- epilogue: y (tf32 bits) in [B,T,DM]
    float invA = 1.0f / l_[0], invB = 1.0f / l_[1];
    int b_ = bh >> 3, h = bh & 7;
    int rowA = q0 + w*16 + r;
    int rowB = rowA + 8;
    #pragma unroll
    for (int ni = 0; ni < 8; ni++) {
        int col = h*HDIM + ni*8 + 2*q;
        *(float2*)&g_y[((size_t)b_*T_ + rowA)*DMODEL + col] =
            make_float2(f2tf_f(o[ni][0]*invA), f2tf_f(o[ni][1]*invA));
        *(float2*)&g_y[((size_t)b_*T_ + rowB)*DMODEL + col] =
            make_float2(f2tf_f(o[ni][2]*invB), f2tf_f(o[ni][3]*invB));
    }
}

// ---------------------------------------------------------------------------
extern "C" void kernel_launch(void* const* d_in, const int* in_sizes, int n_in,
                              void* d_out, int out_size)
{
    const float* x     = (const float*)d_in[0];
    const float* w_qkv = (const float*)d_in[1];
    const float* b_qkv = (const float*)d_in[2];
    const float* w_out = (const float*)d_in[3];
    const float* b_out = (const float*)d_in[4];
    float* out = (float*)d_out;

    cudaFuncSetAttribute(flash_tf32_kernel,
                         cudaFuncAttributeMaxDynamicSharedMemorySize, FLASH_SMEM);
    cudaFuncSetAttribute(gemm_tf32_kernel<3*DMODEL, true,  true >,
                         cudaFuncAttributeMaxDynamicSharedMemorySize, GEMM_SMEM);
    cudaFuncSetAttribute(gemm_tf32_kernel<DMODEL, false, false>,
                         cudaFuncAttributeMaxDynamicSharedMemorySize, GEMM_SMEM);

    gemm_tf32_kernel<3*DMODEL, true,  true ><<<dim3(12, 128), 256, GEMM_SMEM>>>(x, w_qkv, b_qkv, nullptr);
    rope_kernel<<<16384, 256>>>();
    flash_tf32_kernel<<<dim3(64, 32), 128, FLASH_SMEM>>>();
    gemm_tf32_kernel<DMODEL, false, false><<<dim3(4, 128), 256, GEMM_SMEM>>>(nullptr, w_out, b_out, out);
}

// round 10
// speedup vs baseline: 1.3331x; 1.3331x over previous
#include <cuda_runtime.h>

#define B_      8
#define T_      2048
#define DMODEL  512
#define NHEADS  8
#define HDIM    64
#define BT_     (B_*T_)

// Scratch (device globals) — EXACTLY the R2 footprint (128 MiB): proven safe.
__device__ float g_q[B_*NHEADS*T_*HDIM];   // [b,h,t,d] tf32 bits after rope
__device__ float g_k[B_*NHEADS*T_*HDIM];   // [b,h,t,d] tf32 bits after rope
__device__ float g_v[B_*NHEADS*T_*HDIM];   // [b,h,d,t] TRANSPOSED tf32 bits
__device__ float g_y[BT_*DMODEL];          // tf32 bits (flash epilogue)

// ---------------------------------------------------------------------------
// helpers
// ---------------------------------------------------------------------------
__device__ __forceinline__ unsigned f2tf(float x) {
    unsigned u;
    asm("cvt.rna.tf32.f32 %0, %1;" : "=r"(u) : "f"(x));
    return u;
}
__device__ __forceinline__ float f2tf_f(float x) { return __uint_as_float(f2tf(x)); }

__device__ __forceinline__ void mma_tf32(float c[4], const unsigned a[4], const unsigned b[2]) {
    asm volatile(
        "mma.sync.aligned.m16n8k8.row.col.f32.tf32.tf32.f32 "
        "{%0,%1,%2,%3},{%4,%5,%6,%7},{%8,%9},{%0,%1,%2,%3};"
        : "+f"(c[0]), "+f"(c[1]), "+f"(c[2]), "+f"(c[3])
        : "r"(a[0]), "r"(a[1]), "r"(a[2]), "r"(a[3]), "r"(b[0]), "r"(b[1]));
}

__device__ __forceinline__ void ldsm4(unsigned& d0, unsigned& d1, unsigned& d2, unsigned& d3,
                                      unsigned saddr) {
    asm volatile("ldmatrix.sync.aligned.m8n8.x4.shared.b16 {%0,%1,%2,%3}, [%4];"
                 : "=r"(d0), "=r"(d1), "=r"(d2), "=r"(d3) : "r"(saddr));
}

__device__ __forceinline__ void cp16(void* smem, const void* g) {
    unsigned s = (unsigned)__cvta_generic_to_shared(smem);
    asm volatile("cp.async.cg.shared.global [%0], [%1], 16;" :: "r"(s), "l"(g));
}
__device__ __forceinline__ void cp_commit() { asm volatile("cp.async.commit_group;"); }

// ---------------------------------------------------------------------------
// tf32 GEMM — k-step 32, 3-stage cp.async ring, 2 tiles in flight.
// 128x128 tiles, 256 threads (8 warps 2x4), warp tile 64x32, 2 CTAs/SM.
// Half the sync/wait pairs of the k16 version; regs left unconstrained.
// A-fragments via ldmatrix.x4 (pad 36: rows on banks 0,4,..,28 — clean);
// CVT_A=false when A (g_y) is pre-rounded.
// SCATTER: epilogue scatters qkv (V transposed+rounded); else writes Out fp32.
// ---------------------------------------------------------------------------
#define AS_STG (128*36)
#define BS_STG (32*136)
#define GEMM_SMEM (3*(AS_STG + BS_STG)*4)   // 107520 B -> 2 CTAs/SM

template<int N, bool SCATTER, bool CVT_A>
__global__ __launch_bounds__(256) void gemm_tf32_kernel(
    const float* __restrict__ A, const float* __restrict__ W,
    const float* __restrict__ bias, float* __restrict__ Out)
{
    const int K = DMODEL;
    extern __shared__ __align__(16) float smg[];
    float* Asg = smg;                 // [3][128][36]
    float* Bsg = smg + 3*AS_STG;      // [3][32][136]

    int tid  = threadIdx.x;
    int lane = tid & 31, warp = tid >> 5;
    int q = lane & 3, r = lane >> 2;
    int wr = warp >> 2, wc = warp & 3;
    int r0 = blockIdx.y << 7, c0 = blockIdx.x << 7;

    const float* Aptr = SCATTER ? A : g_y;

    unsigned AsB = (unsigned)__cvta_generic_to_shared(Asg);
    unsigned la  = ((lane & 15)*36 + (lane >> 4)*4) * 4;   // A-type LDSM lane offset

    auto issue_tile = [&](int tile) {
        int k0 = tile << 5;
        int st = tile % 3;
        #pragma unroll
        for (int e = 0; e < 4; e++) {
            int idx = e*256 + tid;
            int row = idx >> 3, c4 = (idx & 7) << 2;     // A: 128 x 32
            cp16(&Asg[(st*128 + row)*36 + c4], &Aptr[(size_t)(r0+row)*K + k0 + c4]);
        }
        #pragma unroll
        for (int e = 0; e < 4; e++) {
            int idx = e*256 + tid;
            int kr = idx >> 5, nq4 = (idx & 31) << 2;    // B: 32 x 128
            cp16(&Bsg[st*BS_STG + kr*136 + nq4], &W[(size_t)(k0+kr)*N + c0 + nq4]);
        }
        cp_commit();
    };

    float acc[4][4][4];
    #pragma unroll
    for (int mi = 0; mi < 4; mi++)
        #pragma unroll
        for (int ni = 0; ni < 4; ni++)
            #pragma unroll
            for (int e = 0; e < 4; e++) acc[mi][ni][e] = 0.f;

    // ---- prologue: 2 tiles in flight
    issue_tile(0);
    issue_tile(1);

    for (int it = 0; it < 16; it++) {
        if (it + 1 < 16) asm volatile("cp.async.wait_group 1;");
        else             asm volatile("cp.async.wait_group 0;");
        __syncthreads();                 // tile 'it' visible
        if (it + 2 < 16) issue_tile(it + 2);

        int st = it % 3;
        #pragma unroll
        for (int ks = 0; ks < 4; ks++) {
            unsigned a[4][4], b[4][2];
            #pragma unroll
            for (int mi = 0; mi < 4; mi++) {
                unsigned addr = AsB + ((st*AS_STG + (wr*64 + mi*16)*36 + ks*8) << 2) + la;
                ldsm4(a[mi][0], a[mi][1], a[mi][2], a[mi][3], addr);
                if (CVT_A) {
                    a[mi][0] = f2tf(__uint_as_float(a[mi][0]));
                    a[mi][1] = f2tf(__uint_as_float(a[mi][1]));
                    a[mi][2] = f2tf(__uint_as_float(a[mi][2]));
                    a[mi][3] = f2tf(__uint_as_float(a[mi][3]));
                }
            }
            #pragma unroll
            for (int ni = 0; ni < 4; ni++) {
                int nb2 = wc*32 + ni*8;
                b[ni][0] = f2tf(Bsg[st*BS_STG + (ks*8 + q    )*136 + nb2 + r]);
                b[ni][1] = f2tf(Bsg[st*BS_STG + (ks*8 + q + 4)*136 + nb2 + r]);
            }
            #pragma unroll
            for (int mi = 0; mi < 4; mi++)
                #pragma unroll
                for (int ni = 0; ni < 4; ni++)
                    mma_tf32(acc[mi][ni], a[mi], b[ni]);
        }
    }

    #pragma unroll
    for (int mi = 0; mi < 4; mi++) {
        #pragma unroll
        for (int half = 0; half < 2; half++) {
            int row = r0 + wr*64 + mi*16 + r + half*8;
            #pragma unroll
            for (int ni = 0; ni < 4; ni++) {
                int col = c0 + wc*32 + ni*8 + 2*q;
                float v0 = acc[mi][ni][half*2+0] + bias[col];
                float v1 = acc[mi][ni][half*2+1] + bias[col+1];
                if (SCATTER) {
                    int b_ = row >> 11, t = row & (T_-1);
                    int proj = col >> 9;
                    int dm = col & 511;
                    int h = dm >> 6, d = dm & 63;
                    int bh = (b_<<3) + h;
                    if (proj == 2) {
                        g_v[((size_t)bh*HDIM + d    )*T_ + t] = f2tf_f(v0);
                        g_v[((size_t)bh*HDIM + d + 1)*T_ + t] = f2tf_f(v1);
                    } else {
                        float* dst = (proj == 0) ? g_q : g_k;
                        *(float2*)&dst[((size_t)bh*T_ + t)*HDIM + d] = make_float2(v0, v1);
                    }
                } else {
                    *(float2*)&Out[(size_t)row*N + col] = make_float2(v0, v1);
                }
            }
        }
    }
}

// ---------------------------------------------------------------------------
// RoPE on q (scaled by 1/sqrt(D)) and k, in place; writes tf32 bits
// ---------------------------------------------------------------------------
__global__ void rope_kernel()
{
    int idx = blockIdx.x*blockDim.x + threadIdx.x;   // B*H*T*32
    int i  = idx & 31;
    int t  = (idx >> 5) & (T_-1);
    int bh = idx >> 16;
    float invf = exp2f(-(float)i * 0.4152410118609203f);
    float ang  = (float)t * invf;
    float sn, cs;
    sincosf(ang, &sn, &cs);
    int base = (bh*T_ + t)*HDIM + i;
    float q1 = g_q[base], q2 = g_q[base+32];
    g_q[base]    = f2tf_f((q1*cs - q2*sn) * 0.125f);
    g_q[base+32] = f2tf_f((q2*cs + q1*sn) * 0.125f);
    float k1 = g_k[base], k2 = g_k[base+32];
    g_k[base]    = f2tf_f(k1*cs - k2*sn);
    g_k[base+32] = f2tf_f(k2*cs + k1*sn);
}

// ---------------------------------------------------------------------------
// Causal flash attention — K and V both SINGLE-buffered -> 54.3KB smem
// -> 4 CTAs/SM. K(t+1)+V(t+1) issued together after the post-PV sync.
//   Kn [64][68]  natural [key][d]    -> S-mma B frags via ldmatrix.x4
//   Vn [64][68]  TRANSPOSED [d][key] -> PV-mma B frags via ldmatrix.x4
//   QP [64][76]  Q staging / per-warp P -> A frags via ldmatrix.x4
// ---------------------------------------------------------------------------
#define KN_S 68
#define VN_S 68
#define QP_S 76
#define FLASH_SMEM ((64*KN_S + 64*VN_S + 64*QP_S)*4)   // 54272 B

__global__ __launch_bounds__(128, 4) void flash_tf32_kernel()
{
    extern __shared__ __align__(16) float sm[];
    float* Kn = sm;
    float* Vn = sm + 64*KN_S;
    float* QP = sm + 64*KN_S + 64*VN_S;

    int tid  = threadIdx.x;
    int lane = tid & 31, w = tid >> 5;
    int q = lane & 3, r = lane >> 2;
    int bh = blockIdx.x;
    int qt = 31 - (int)blockIdx.y;      // heavy tiles first
    int q0 = qt << 6;

    unsigned smB = (unsigned)__cvta_generic_to_shared(sm);
    unsigned KnB = smB;
    unsigned VnB = smB + 64*KN_S*4;
    unsigned QPB = smB + (64*KN_S + 64*VN_S)*4;
    unsigned lb  = ((lane & 7)*KN_S + (lane >> 3)*4) * 4;   // B-type LDSM (KN_S==VN_S)
    unsigned lpa = ((lane & 15)*QP_S + (lane >> 4)*4) * 4;  // A-type LDSM in QP

    const float* Kbase = g_k + (size_t)bh*T_*HDIM;          // [key][d]
    const float* Vbase = g_v + (size_t)bh*HDIM*T_;          // [d][key]

    // ---- prefetch K0 + V0 (one group)
    #pragma unroll
    for (int e = 0; e < 8; e++) {
        int idx = e*128 + tid;
        int rr = idx >> 4, c4 = (idx & 15) << 2;
        cp16(&Kn[rr*KN_S + c4], &Kbase[rr*HDIM + c4]);
        cp16(&Vn[rr*VN_S + c4], &Vbase[(size_t)rr*T_ + c4]);
    }
    cp_commit();

    // ---- stage Q tile (tf32 bits already)
    const float* Qg = g_q + ((size_t)bh*T_ + q0)*HDIM;
    #pragma unroll
    for (int it = 0; it < 8; it++) {
        int idx = it*128 + tid;
        int rr = idx >> 4, cc = (idx & 15) << 2;
        *(float4*)&QP[rr*QP_S + cc] = *(const float4*)&Qg[rr*HDIM + cc];
    }
    __syncthreads();

    // ---- Q fragments in registers (A-type ldmatrix, 8x)
    unsigned qa[8][4];
    #pragma unroll
    for (int kk = 0; kk < 8; kk++) {
        unsigned addr = QPB + ((w*16*QP_S + kk*8) << 2) + lpa;
        ldsm4(qa[kk][0], qa[kk][1], qa[kk][2], qa[kk][3], addr);
    }

    float o[8][4];
    float m_[2] = {-1e30f, -1e30f};
    float l_[2] = {0.f, 0.f};
    #pragma unroll
    for (int ni = 0; ni < 8; ni++)
        #pragma unroll
        for (int e = 0; e < 4; e++) o[ni][e] = 0.f;

    for (int kt = 0; kt <= qt; kt++) {
        asm volatile("cp.async.wait_group 0;");   // K(t), V(t) arrived
        __syncthreads();

        // ---- S = Q @ K^T
        float s[8][4];
        #pragma unroll
        for (int ni = 0; ni < 8; ni++)
            #pragma unroll
            for (int e = 0; e < 4; e++) s[ni][e] = 0.f;

        #pragma unroll
        for (int ni = 0; ni < 8; ni++) {
            #pragma unroll
            for (int kp = 0; kp < 4; kp++) {
                unsigned b0, b1, b2, b3;
                ldsm4(b0, b1, b2, b3, KnB + ((ni*8*KN_S + kp*16) << 2) + lb);
                unsigned bb0[2] = {b0, b1};
                unsigned bb1[2] = {b2, b3};
                mma_tf32(s[ni], qa[2*kp],     bb0);
                mma_tf32(s[ni], qa[2*kp + 1], bb1);
            }
        }

        // ---- causal mask (diagonal tile only)
        if (kt == qt) {
            int rowA = q0 + w*16 + r;
            int rowB = rowA + 8;
            int k0 = kt << 6;
            #pragma unroll
            for (int ni = 0; ni < 8; ni++) {
                int colb = k0 + ni*8 + 2*q;
                if (colb     > rowA) s[ni][0] = -1e30f;
                if (colb + 1 > rowA) s[ni][1] = -1e30f;
                if (colb     > rowB) s[ni][2] = -1e30f;
                if (colb + 1 > rowB) s[ni][3] = -1e30f;
            }
        }

        // ---- online softmax
        float mxA = -1e30f, mxB = -1e30f;
        #pragma unroll
        for (int ni = 0; ni < 8; ni++) {
            mxA = fmaxf(mxA, fmaxf(s[ni][0], s[ni][1]));
            mxB = fmaxf(mxB, fmaxf(s[ni][2], s[ni][3]));
        }
        mxA = fmaxf(mxA, __shfl_xor_sync(0xffffffffu, mxA, 1));
        mxA = fmaxf(mxA, __shfl_xor_sync(0xffffffffu, mxA, 2));
        mxB = fmaxf(mxB, __shfl_xor_sync(0xffffffffu, mxB, 1));
        mxB = fmaxf(mxB, __shfl_xor_sync(0xffffffffu, mxB, 2));
        float mnA = fmaxf(m_[0], mxA), mnB = fmaxf(m_[1], mxB);
        float alA = __expf(m_[0] - mnA), alB = __expf(m_[1] - mnB);
        m_[0] = mnA; m_[1] = mnB;
        float sA = 0.f, sB = 0.f;
        #pragma unroll
        for (int ni = 0; ni < 8; ni++) {
            s[ni][0] = __expf(s[ni][0] - mnA);
            s[ni][1] = __expf(s[ni][1] - mnA);
            s[ni][2] = __expf(s[ni][2] - mnB);
            s[ni][3] = __expf(s[ni][3] - mnB);
            sA += s[ni][0] + s[ni][1];
            sB += s[ni][2] + s[ni][3];
        }
        sA += __shfl_xor_sync(0xffffffffu, sA, 1);
        sA += __shfl_xor_sync(0xffffffffu, sA, 2);
        sB += __shfl_xor_sync(0xffffffffu, sB, 1);
        sB += __shfl_xor_sync(0xffffffffu, sB, 2);
        l_[0] = l_[0]*alA + sA;
        l_[1] = l_[1]*alB + sB;
        #pragma unroll
        for (int ni = 0; ni < 8; ni++) {
            o[ni][0] *= alA; o[ni][1] *= alA;
            o[ni][2] *= alB; o[ni][3] *= alB;
        }

        // ---- stage P (tf32 bits) into per-warp rows of QP
        __syncwarp();
        {
            int rb = w*16 + r;
            #pragma unroll
            for (int ni = 0; ni < 8; ni++) {
                *(float2*)&QP[(rb    )*QP_S + ni*8 + 2*q] =
                    make_float2(f2tf_f(s[ni][0]), f2tf_f(s[ni][1]));
                *(float2*)&QP[(rb + 8)*QP_S + ni*8 + 2*q] =
                    make_float2(f2tf_f(s[ni][2]), f2tf_f(s[ni][3]));
            }
        }
        __syncwarp();

        // ---- O += P @ V  (P: A-type ldmatrix; V: B-type ldmatrix)
        #pragma unroll
        for (int kp = 0; kp < 4; kp++) {
            unsigned paA[4], paB[4];
            ldsm4(paA[0], paA[1], paA[2], paA[3],
                  QPB + ((w*16*QP_S + (2*kp    )*8) << 2) + lpa);
            ldsm4(paB[0], paB[1], paB[2], paB[3],
                  QPB + ((w*16*QP_S + (2*kp + 1)*8) << 2) + lpa);
            #pragma unroll
            for (int ni = 0; ni < 8; ni++) {
                unsigned v0, v1, v2, v3;
                ldsm4(v0, v1, v2, v3, VnB + ((ni*8*VN_S + kp*16) << 2) + lb);
                unsigned vb0[2] = {v0, v1};
                unsigned vb1[2] = {v2, v3};
                mma_tf32(o[ni], paA, vb0);
                mma_tf32(o[ni], paB, vb1);
            }
        }

        // ---- K(t+1) + V(t+1) after ALL warps finished S(t) and PV(t)
        if (kt < qt) {
            __syncthreads();
            int k1 = (kt + 1) << 6;
            const float* Kg1 = Kbase + (size_t)k1*HDIM;
            #pragma unroll
            for (int e = 0; e < 8; e++) {
                int idx = e*128 + tid;
                int rr = idx >> 4, c4 = (idx & 15) << 2;
                cp16(&Kn[rr*KN_S + c4], &Kg1[rr*HDIM + c4]);
                cp16(&Vn[rr*VN_S + c4], &Vbase[(size_t)rr*T_ + k1 + c4]);
            }
            cp_commit();
        }
    }

    // ---- epilogue: y (tf32 bits) in [B,T,DM]
    float invA = 1.0f / l_[0], invB = 1.0f / l_[1];
    int b_ = bh >> 3, h = bh & 7;
    int rowA = q0 + w*16 + r;
    int rowB = rowA + 8;
    #pragma unroll
    for (int ni = 0; ni < 8; ni++) {
        int col = h*HDIM + ni*8 + 2*q;
        *(float2*)&g_y[((size_t)b_*T_ + rowA)*DMODEL + col] =
            make_float2(f2tf_f(o[ni][0]*invA), f2tf_f(o[ni][1]*invA));
        *(float2*)&g_y[((size_t)b_*T_ + rowB)*DMODEL + col] =
            make_float2(f2tf_f(o[ni][2]*invB), f2tf_f(o[ni][3]*invB));
    }
}

// ---------------------------------------------------------------------------
extern "C" void kernel_launch(void* const* d_in, const int* in_sizes, int n_in,
                              void* d_out, int out_size)
{
    const float* x     = (const float*)d_in[0];
    const float* w_qkv = (const float*)d_in[1];
    const float* b_qkv = (const float*)d_in[2];
    const float* w_out = (const float*)d_in[3];
    const float* b_out = (const float*)d_in[4];
    float* out = (float*)d_out;

    cudaFuncSetAttribute(flash_tf32_kernel,
                         cudaFuncAttributeMaxDynamicSharedMemorySize, FLASH_SMEM);
    cudaFuncSetAttribute(gemm_tf32_kernel<3*DMODEL, true,  true >,
                         cudaFuncAttributeMaxDynamicSharedMemorySize, GEMM_SMEM);
    cudaFuncSetAttribute(gemm_tf32_kernel<DMODEL, false, false>,
                         cudaFuncAttributeMaxDynamicSharedMemorySize, GEMM_SMEM);

    gemm_tf32_kernel<3*DMODEL, true,  true ><<<dim3(12, 128), 256, GEMM_SMEM>>>(x, w_qkv, b_qkv, nullptr);
    rope_kernel<<<16384, 256>>>();
    flash_tf32_kernel<<<dim3(64, 32), 128, FLASH_SMEM>>>();
    gemm_tf32_kernel<DMODEL, false, false><<<dim3(4, 128), 256, GEMM_SMEM>>>(nullptr, w_out, b_out, out);
}